// round 16
// baseline (speedup 1.0000x reference)
#include <cuda_runtime.h>
#include <cuda_fp16.h>

#define BB 16
#define NN 127
#define SS 32
#define EE 16
#define VV 128
#define TT 128   // N+1 memory slots
#define LL 128

__global__ __launch_bounds__(256, 7)
void memnet_fused2(const float* __restrict__ node_fts,
                   const float* __restrict__ edge_fts,
                   const float* __restrict__ graph_fts,
                   const float* __restrict__ adj_mat,
                   const float* __restrict__ query_biases,
                   const float* __restrict__ stories_biases,
                   const float* __restrict__ output_biases,
                   const float* __restrict__ memory_contents,
                   const float* __restrict__ W_out,
                   const float* __restrict__ W_fin,
                   float* __restrict__ out)
{
    __shared__ __align__(16) unsigned int sidxw[2][TT * 8];  // u8 indices; ALIASED as `part` in I
    __shared__ __align__(16) __half obtH[VV * 24];           // ob fp16, v-major, stride 24 (48B, 16B-aligned rows)
    __shared__ __half2 QtH[2][VV];                           // packed (Q0,Q1) per half
    __shared__ float logits[2][TT];                          // logits -> exp (unnormalized)
    __shared__ unsigned char nzlist[2][TT];
    __shared__ unsigned char zrow[2][TT];
    __shared__ int warpcnt[2][4];
    __shared__ int nzcnt[2];
    __shared__ int qidx[3][SS];                              // A, B, graph
    __shared__ float uvec[3][EE];
    __shared__ float hs[2][EE];
    __shared__ float hsg[EE];
    __shared__ float xsum[2][LL];
    __shared__ __align__(16) float red0[8 * 16];             // [half*4+wl][e]
    __shared__ __align__(16) float red1[8 * 16];
    __shared__ float redp[8];
    __shared__ float wred[2][4];

    const int tid = threadIdx.x;
    const int cta = blockIdx.x;
    const int b = cta >> 6;
    const int c = cta & 63;
    const int tA = 2 * c;
    const int tBr = 2 * c + 1;
    const bool stB = (tBr < NN);
    const int tB = stB ? tBr : (NN - 1);     // clamp (dup work, store guarded)

    const int half = tid >> 7;               // 0 = row A, 1 = row B
    const int ht = tid & 127;
    const int myT = half ? tB : tA;

    // ---------------- A: adj flags + ballot (regs kept for B) ----------------
    bool nz = false;
    if (ht < NN) nz = (adj_mat[(b * NN + myT) * NN + ht] != 0.f);
    zrow[half][ht] = nz ? 0 : 1;
    unsigned mask = __ballot_sync(0xFFFFFFFFu, nz);
    const int w4 = (tid >> 5) & 3;
    if ((tid & 31) == 0) warpcnt[half][w4] = __popc(mask);
    const int pos = __popc(mask & ((1u << (tid & 31)) - 1u));
    __syncthreads();

    // ---------------- B: nzlist + nzcnt + query idx + ob table ----------------
    {
        int off = 0;
        #pragma unroll
        for (int i = 0; i < 4; i++) if (i < w4) off += warpcnt[half][i];
        if (nz) nzlist[half][off + pos] = (unsigned char)ht;
        if (ht == 0)
            nzcnt[half] = warpcnt[half][0] + warpcnt[half][1] + warpcnt[half][2] + warpcnt[half][3];
    }
    if (tid < 96) {
        int which = tid >> 5, s = tid & 31;
        float qv;
        if (which == 0)      qv = node_fts[(b * NN + tA) * SS + s];
        else if (which == 1) qv = node_fts[(b * NN + tB) * SS + s];
        else                 qv = graph_fts[b * SS + s];
        qidx[which][s] = min(max((int)qv, 0), VV - 1);
    }
    for (int i = tid; i < VV * EE; i += 256) {
        int v = i >> 4, e = i & 15;
        obtH[v * 24 + e] = __float2half((v < VV - 1) ? output_biases[v * EE + e] : 0.f);
    }
    __syncthreads();

    const int K0 = nzcnt[0], K1 = nzcnt[1];

    // ---------------- C: u vectors (48 thr) + edge staging (rest) ----------------
    if (tid < 48) {
        int which = tid >> 4, e = tid & 15;
        float ae = (float)(e - 7) * (1.f / 128.f);
        float acc = 0.f;
        #pragma unroll
        for (int s = 0; s < SS; s++) {
            int idx = qidx[which][s];
            float qv = (idx < VV - 1) ? query_biases[idx * EE + e] : 0.f;
            acc += qv * (1.f + ae * (float)(s - 15));
        }
        uvec[which][e] = acc;
    } else if (tid < 128) {
        for (int slot = tid - 48; slot < K0 * 8; slot += 80) {
            int r = slot >> 3, j = slot & 7;
            int m = nzlist[0][r];
            float4 ef4 = ((const float4*)edge_fts)[((b * NN + tA) * NN + m) * 8 + j];
            unsigned int w;
            w  = (unsigned int)min(max((int)ef4.x, 0), 127);
            w |= (unsigned int)min(max((int)ef4.y, 0), 127) << 8;
            w |= (unsigned int)min(max((int)ef4.z, 0), 127) << 16;
            w |= (unsigned int)min(max((int)ef4.w, 0), 127) << 24;
            sidxw[0][m * 8 + j] = w;
        }
    } else {
        for (int slot = ht; slot < K1 * 8; slot += 128) {
            int r = slot >> 3, j = slot & 7;
            int m = nzlist[1][r];
            float4 ef4 = ((const float4*)edge_fts)[((b * NN + tB) * NN + m) * 8 + j];
            unsigned int w;
            w  = (unsigned int)min(max((int)ef4.x, 0), 127);
            w |= (unsigned int)min(max((int)ef4.y, 0), 127) << 8;
            w |= (unsigned int)min(max((int)ef4.z, 0), 127) << 16;
            w |= (unsigned int)min(max((int)ef4.w, 0), 127) << 24;
            sidxw[1][m * 8 + j] = w;
        }
    }
    __syncthreads();

    // ---------------- C2: Qt tables (fp16-packed) + logit init, thread=(half, ht) ----------------
    {
        int v = ht;
        float q0 = 0.f, q1 = 0.f;
        if (v < VV - 1) {
            #pragma unroll
            for (int e = 0; e < EE; e++) {
                float sv = stories_biases[v * EE + e];
                float ue = uvec[half][e];
                q0 += sv * ue;
                q1 += sv * ue * ((float)(e - 7) * (1.f / 128.f));
            }
        }
        QtH[half][v] = __floats2half2_rn(q0, q1);
        float acc = 0.f;
        #pragma unroll
        for (int e = 0; e < EE; e++)
            acc += memory_contents[ht * EE + e] * uvec[half][e];
        logits[half][ht] = acc;
    }
    __syncthreads();

    // ---------------- D+E fused: pass-1 gathers -> logit -> exp (own slot only) ----------------
    {
        int m = ht;
        float acc;
        if (zrow[half][m]) {
            float2 q0 = __half22float2(QtH[half][0]);
            acc = 32.f * q0.x + 16.f * q0.y;
        } else {
            acc = 0.f;
            #pragma unroll
            for (int sw = 0; sw < 8; sw++) {
                unsigned int wd = sidxw[half][m * 8 + sw];
                #pragma unroll
                for (int k = 0; k < 4; k++) {
                    int idx = (wd >> (8 * k)) & 255;
                    float2 q = __half22float2(QtH[half][idx]);
                    int s = sw * 4 + k;
                    acc += q.x + (float)(s - 15) * q.y;
                }
            }
        }
        float ev = __expf(logits[half][m] + acc);   // no max shift: logits are tiny
        logits[half][m] = ev;
        float sm = ev;
        #pragma unroll
        for (int o = 16; o; o >>= 1) sm += __shfl_xor_sync(0xFFFFFFFFu, sm, o);
        if ((tid & 31) == 0) wred[half][w4] = sm;
    }
    __syncthreads();

    // ---------------- F: pass-2 gathers, LDS.128 (8 e's/lane), inv folded in ----------------
    // lane = (sp<<1)|eq : sp 0..15 covers 16 s-positions per step, eq picks 8 e's (16B).
    {
        int w = tid >> 5;
        int fh = w >> 2, wl = w & 3;
        int lane = tid & 31, sp = lane >> 1, eq = lane & 1;
        int Kf = fh ? K1 : K0;
        float inv = 1.f / (wred[fh][0] + wred[fh][1] + wred[fh][2] + wred[fh][3]);
        float4 a0lo = make_float4(0.f, 0.f, 0.f, 0.f);
        float4 a0hi = make_float4(0.f, 0.f, 0.f, 0.f);
        float4 a1lo = make_float4(0.f, 0.f, 0.f, 0.f);
        float4 a1hi = make_float4(0.f, 0.f, 0.f, 0.f);
        float accp = 0.f;
        for (int r = wl; r < Kf; r += 4) {
            int m = nzlist[fh][r];
            float pm = logits[fh][m] * inv;
            accp += pm;                   // lane 0's copy used
            #pragma unroll
            for (int it = 0; it < 2; it++) {
                int s = it * 16 + sp;
                unsigned int wd = sidxw[fh][m * 8 + (s >> 2)];
                int idx = (wd >> (8 * (s & 3))) & 255;
                uint4 uv = *(const uint4*)&obtH[idx * 24 + eq * 8];  // 16B-aligned (stride 48B)
                float2 f0 = __half22float2(*(__half2*)&uv.x);
                float2 f1 = __half22float2(*(__half2*)&uv.y);
                float2 f2 = __half22float2(*(__half2*)&uv.z);
                float2 f3 = __half22float2(*(__half2*)&uv.w);
                float c1 = pm * (float)(s - 15);
                a0lo.x = fmaf(f0.x, pm, a0lo.x); a0lo.y = fmaf(f0.y, pm, a0lo.y);
                a0lo.z = fmaf(f1.x, pm, a0lo.z); a0lo.w = fmaf(f1.y, pm, a0lo.w);
                a0hi.x = fmaf(f2.x, pm, a0hi.x); a0hi.y = fmaf(f2.y, pm, a0hi.y);
                a0hi.z = fmaf(f3.x, pm, a0hi.z); a0hi.w = fmaf(f3.y, pm, a0hi.w);
                a1lo.x = fmaf(f0.x, c1, a1lo.x); a1lo.y = fmaf(f0.y, c1, a1lo.y);
                a1lo.z = fmaf(f1.x, c1, a1lo.z); a1lo.w = fmaf(f1.y, c1, a1lo.w);
                a1hi.x = fmaf(f2.x, c1, a1hi.x); a1hi.y = fmaf(f2.y, c1, a1hi.y);
                a1hi.z = fmaf(f3.x, c1, a1hi.z); a1hi.w = fmaf(f3.y, c1, a1hi.w);
            }
        }
        // reduce over the 16 sp-lanes sharing each eq (xor 2,4,8,16)
        #pragma unroll
        for (int o = 16; o >= 2; o >>= 1) {
            a0lo.x += __shfl_xor_sync(0xFFFFFFFFu, a0lo.x, o);
            a0lo.y += __shfl_xor_sync(0xFFFFFFFFu, a0lo.y, o);
            a0lo.z += __shfl_xor_sync(0xFFFFFFFFu, a0lo.z, o);
            a0lo.w += __shfl_xor_sync(0xFFFFFFFFu, a0lo.w, o);
            a0hi.x += __shfl_xor_sync(0xFFFFFFFFu, a0hi.x, o);
            a0hi.y += __shfl_xor_sync(0xFFFFFFFFu, a0hi.y, o);
            a0hi.z += __shfl_xor_sync(0xFFFFFFFFu, a0hi.z, o);
            a0hi.w += __shfl_xor_sync(0xFFFFFFFFu, a0hi.w, o);
            a1lo.x += __shfl_xor_sync(0xFFFFFFFFu, a1lo.x, o);
            a1lo.y += __shfl_xor_sync(0xFFFFFFFFu, a1lo.y, o);
            a1lo.z += __shfl_xor_sync(0xFFFFFFFFu, a1lo.z, o);
            a1lo.w += __shfl_xor_sync(0xFFFFFFFFu, a1lo.w, o);
            a1hi.x += __shfl_xor_sync(0xFFFFFFFFu, a1hi.x, o);
            a1hi.y += __shfl_xor_sync(0xFFFFFFFFu, a1hi.y, o);
            a1hi.z += __shfl_xor_sync(0xFFFFFFFFu, a1hi.z, o);
            a1hi.w += __shfl_xor_sync(0xFFFFFFFFu, a1hi.w, o);
        }
        if (lane < 2) {
            *(float4*)&red0[w * 16 + eq * 8]     = a0lo;
            *(float4*)&red0[w * 16 + eq * 8 + 4] = a0hi;
            *(float4*)&red1[w * 16 + eq * 8]     = a1lo;
            *(float4*)&red1[w * 16 + eq * 8 + 4] = a1hi;
        }
        if (lane == 0) redp[w] = accp;
    }
    __syncthreads();

    // ---------------- G: combine -> hvec per half + closed-form graph hvec ----------------
    if (tid < 32) {
        int gh = tid >> 4, e = tid & 15;
        float O0 = 0.f, O1 = 0.f, sp = 0.f;
        #pragma unroll
        for (int wl = 0; wl < 4; wl++) {
            O0 += red0[(gh * 4 + wl) * 16 + e];
            O1 += red1[(gh * 4 + wl) * 16 + e];
            sp += redp[gh * 4 + wl];
        }
        float Z = 1.f - sp;                       // prob mass on zero rows
        float ob0 = output_biases[e];             // fp32 row v=0
        O0 += Z * 32.f * ob0;
        O1 += Z * 16.f * ob0;
        float ae = (float)(e - 7) * (1.f / 128.f);
        hs[gh][e] = uvec[gh][e] + O0 + ae * O1;
    } else if (tid < 48) {
        // graph row: stories all-zero -> o independent of probs (closed form)
        int e = tid - 32;
        float ae = (float)(e - 7) * (1.f / 128.f);
        hsg[e] = uvec[2][e] + (32.f + 16.f * ae) * output_biases[e];
    }
    __syncthreads();

    // ---------------- H: xsum[half][l] = relu(h_half@W_out) + relu(h_g@W_out) ----------------
    {
        int l = ht;
        float accO = 0.f, accG = 0.f;
        #pragma unroll
        for (int e = 0; e < EE; e++) {
            float w = W_out[e * LL + l];
            accO = fmaf(hs[half][e], w, accO);
            accG = fmaf(hsg[e], w, accG);
        }
        xsum[half][l] = fmaxf(accO, 0.f) + fmaxf(accG, 0.f);
    }
    __syncthreads();

    // ---------------- I: both rows @ W_fin, wv loads shared; partials in dead sidxw ----------------
    {
        int vq = tid & 31, lh = tid >> 5;          // 8 lh groups x 16 l
        const float4* wp = (const float4*)W_fin + (lh * 16) * 32 + vq;
        float4 aA = make_float4(0.f, 0.f, 0.f, 0.f);
        float4 aB = make_float4(0.f, 0.f, 0.f, 0.f);
        int l = lh * 16;
        #pragma unroll 1
        for (int ch = 0; ch < 8; ch++) {
            float4 w0 = wp[0];
            float4 w1 = wp[32];
            float xA0 = xsum[0][l], xA1 = xsum[0][l + 1];
            float xB0 = xsum[1][l], xB1 = xsum[1][l + 1];
            aA.x = fmaf(w0.x, xA0, aA.x); aA.y = fmaf(w0.y, xA0, aA.y);
            aA.z = fmaf(w0.z, xA0, aA.z); aA.w = fmaf(w0.w, xA0, aA.w);
            aB.x = fmaf(w0.x, xB0, aB.x); aB.y = fmaf(w0.y, xB0, aB.y);
            aB.z = fmaf(w0.z, xB0, aB.z); aB.w = fmaf(w0.w, xB0, aB.w);
            aA.x = fmaf(w1.x, xA1, aA.x); aA.y = fmaf(w1.y, xA1, aA.y);
            aA.z = fmaf(w1.z, xA1, aA.z); aA.w = fmaf(w1.w, xA1, aA.w);
            aB.x = fmaf(w1.x, xB1, aB.x); aB.y = fmaf(w1.y, xB1, aB.y);
            aB.z = fmaf(w1.z, xB1, aB.z); aB.w = fmaf(w1.w, xB1, aB.w);
            wp += 64;
            l += 2;
        }
        float4* part = (float4*)&sidxw[0][0];      // sidxw dead after F; 7.2KB used of 8KB
        if (lh > 0) {
            part[((lh - 1) * 2 + 0) * 32 + vq] = aA;
            part[((lh - 1) * 2 + 1) * 32 + vq] = aB;
        }
        __syncthreads();
        if (lh == 0) {
            #pragma unroll
            for (int j = 0; j < 7; j++) {
                float4 pa = part[(j * 2 + 0) * 32 + vq];
                float4 pb = part[(j * 2 + 1) * 32 + vq];
                aA.x += pa.x; aA.y += pa.y; aA.z += pa.z; aA.w += pa.w;
                aB.x += pb.x; aB.y += pb.y; aB.z += pb.z; aB.w += pb.w;
            }
            *(float4*)&out[(b * NN + tA) * VV + vq * 4] = aA;
            if (stB) *(float4*)&out[(b * NN + tBr) * VV + vq * 4] = aB;
        }
    }
}

extern "C" void kernel_launch(void* const* d_in, const int* in_sizes, int n_in,
                              void* d_out, int out_size)
{
    (void)in_sizes; (void)n_in; (void)out_size;
    const float* node_fts        = (const float*)d_in[0];
    const float* edge_fts        = (const float*)d_in[1];
    const float* graph_fts       = (const float*)d_in[2];
    const float* adj_mat         = (const float*)d_in[3];
    // d_in[4] hidden (unused), d_in[5] enc (computed analytically, exact)
    const float* query_biases    = (const float*)d_in[6];
    const float* stories_biases  = (const float*)d_in[7];
    const float* output_biases   = (const float*)d_in[8];
    const float* memory_contents = (const float*)d_in[9];
    // d_in[10] W_int unused (num_hops == 1)
    const float* W_out           = (const float*)d_in[11];
    const float* W_fin           = (const float*)d_in[12];

    memnet_fused2<<<BB * 64, 256>>>(node_fts, edge_fts, graph_fts, adj_mat,
                                    query_biases, stories_biases, output_biases,
                                    memory_contents, W_out, W_fin, (float*)d_out);
}

// round 17
// speedup vs baseline: 1.0487x; 1.0487x over previous
#include <cuda_runtime.h>
#include <cuda_fp16.h>

#define BB 16
#define NN 127
#define SS 32
#define EE 16
#define VV 128
#define TT 128   // N+1 memory slots
#define LL 128

__global__ __launch_bounds__(256, 8)
void memnet_fused2(const float* __restrict__ node_fts,
                   const float* __restrict__ edge_fts,
                   const float* __restrict__ graph_fts,
                   const float* __restrict__ adj_mat,
                   const float* __restrict__ query_biases,
                   const float* __restrict__ stories_biases,
                   const float* __restrict__ output_biases,
                   const float* __restrict__ memory_contents,
                   const float* __restrict__ W_out,
                   const float* __restrict__ W_fin,
                   float* __restrict__ out)
{
    __shared__ __align__(16) unsigned int sidxw[2][TT * 8];  // u8 indices; ALIASED as `part` in I
    __shared__ __align__(16) __half obtH[VV * 20];           // ob fp16, v-major, stride 20
    __shared__ __half2 QtH[2][VV];                           // packed (Q0,Q1) per half
    __shared__ float logits[2][TT];                          // logits -> exp (unnormalized)
    __shared__ unsigned char nzlist[2][TT];
    __shared__ unsigned char zrow[2][TT];
    __shared__ int warpcnt[2][4];
    __shared__ int nzcnt[2];
    __shared__ int qidx[3][SS];                              // A, B, graph
    __shared__ float uvec[3][EE];
    __shared__ float hs[2][EE];
    __shared__ float hsg[EE];
    __shared__ float xsum[2][LL];
    __shared__ __align__(16) float red0[8 * 16];             // [half*4+wl][e]
    __shared__ __align__(16) float red1[8 * 16];
    __shared__ float redp[8];
    __shared__ float wred[2][4];

    const int tid = threadIdx.x;
    const int cta = blockIdx.x;
    const int b = cta >> 6;
    const int c = cta & 63;
    const int tA = 2 * c;
    const int tBr = 2 * c + 1;
    const bool stB = (tBr < NN);
    const int tB = stB ? tBr : (NN - 1);     // clamp (dup work, store guarded)

    const int half = tid >> 7;               // 0 = row A, 1 = row B
    const int ht = tid & 127;
    const int myT = half ? tB : tA;

    // ---------------- A: adj flags + ballot (regs kept for B) ----------------
    bool nz = false;
    if (ht < NN) nz = (adj_mat[(b * NN + myT) * NN + ht] != 0.f);
    zrow[half][ht] = nz ? 0 : 1;
    unsigned mask = __ballot_sync(0xFFFFFFFFu, nz);
    const int w4 = (tid >> 5) & 3;
    if ((tid & 31) == 0) warpcnt[half][w4] = __popc(mask);
    const int pos = __popc(mask & ((1u << (tid & 31)) - 1u));
    __syncthreads();

    // ---------------- B: nzlist + nzcnt + query idx + ob table ----------------
    {
        int off = 0;
        #pragma unroll
        for (int i = 0; i < 4; i++) if (i < w4) off += warpcnt[half][i];
        if (nz) nzlist[half][off + pos] = (unsigned char)ht;
        if (ht == 0)
            nzcnt[half] = warpcnt[half][0] + warpcnt[half][1] + warpcnt[half][2] + warpcnt[half][3];
    }
    if (tid < 96) {
        int which = tid >> 5, s = tid & 31;
        float qv;
        if (which == 0)      qv = node_fts[(b * NN + tA) * SS + s];
        else if (which == 1) qv = node_fts[(b * NN + tB) * SS + s];
        else                 qv = graph_fts[b * SS + s];
        qidx[which][s] = min(max((int)qv, 0), VV - 1);
    }
    for (int i = tid; i < VV * EE; i += 256) {
        int v = i >> 4, e = i & 15;
        obtH[v * 20 + e] = __float2half((v < VV - 1) ? output_biases[v * EE + e] : 0.f);
    }
    __syncthreads();

    const int K0 = nzcnt[0], K1 = nzcnt[1];

    // ---------------- C: u vectors (48 thr) + edge staging (rest) ----------------
    if (tid < 48) {
        int which = tid >> 4, e = tid & 15;
        float ae = (float)(e - 7) * (1.f / 128.f);
        float acc = 0.f;
        #pragma unroll
        for (int s = 0; s < SS; s++) {
            int idx = qidx[which][s];
            float qv = (idx < VV - 1) ? query_biases[idx * EE + e] : 0.f;
            acc += qv * (1.f + ae * (float)(s - 15));
        }
        uvec[which][e] = acc;
    } else if (tid < 128) {
        for (int slot = tid - 48; slot < K0 * 8; slot += 80) {
            int r = slot >> 3, j = slot & 7;
            int m = nzlist[0][r];
            float4 ef4 = ((const float4*)edge_fts)[((b * NN + tA) * NN + m) * 8 + j];
            unsigned int w;
            w  = (unsigned int)min(max((int)ef4.x, 0), 127);
            w |= (unsigned int)min(max((int)ef4.y, 0), 127) << 8;
            w |= (unsigned int)min(max((int)ef4.z, 0), 127) << 16;
            w |= (unsigned int)min(max((int)ef4.w, 0), 127) << 24;
            sidxw[0][m * 8 + j] = w;
        }
    } else {
        for (int slot = ht; slot < K1 * 8; slot += 128) {
            int r = slot >> 3, j = slot & 7;
            int m = nzlist[1][r];
            float4 ef4 = ((const float4*)edge_fts)[((b * NN + tB) * NN + m) * 8 + j];
            unsigned int w;
            w  = (unsigned int)min(max((int)ef4.x, 0), 127);
            w |= (unsigned int)min(max((int)ef4.y, 0), 127) << 8;
            w |= (unsigned int)min(max((int)ef4.z, 0), 127) << 16;
            w |= (unsigned int)min(max((int)ef4.w, 0), 127) << 24;
            sidxw[1][m * 8 + j] = w;
        }
    }
    __syncthreads();

    // ---------------- C2: Qt tables (fp16-packed) + logit init, thread=(half, ht) ----------------
    {
        int v = ht;
        float q0 = 0.f, q1 = 0.f;
        if (v < VV - 1) {
            #pragma unroll
            for (int e = 0; e < EE; e++) {
                float sv = stories_biases[v * EE + e];
                float ue = uvec[half][e];
                q0 += sv * ue;
                q1 += sv * ue * ((float)(e - 7) * (1.f / 128.f));
            }
        }
        QtH[half][v] = __floats2half2_rn(q0, q1);
        float acc = 0.f;
        #pragma unroll
        for (int e = 0; e < EE; e++)
            acc += memory_contents[ht * EE + e] * uvec[half][e];
        logits[half][ht] = acc;
    }
    __syncthreads();

    // ---------------- D+E fused: pass-1 gathers -> logit -> exp -> warp sums ----------------
    {
        int m = ht;
        float acc;
        if (zrow[half][m]) {
            float2 q0 = __half22float2(QtH[half][0]);
            acc = 32.f * q0.x + 16.f * q0.y;
        } else {
            acc = 0.f;
            #pragma unroll
            for (int sw = 0; sw < 8; sw++) {
                unsigned int wd = sidxw[half][m * 8 + sw];
                #pragma unroll
                for (int k = 0; k < 4; k++) {
                    int idx = (wd >> (8 * k)) & 255;
                    float2 q = __half22float2(QtH[half][idx]);
                    int s = sw * 4 + k;
                    acc += q.x + (float)(s - 15) * q.y;
                }
            }
        }
        float ev = __expf(logits[half][m] + acc);   // no max shift: logits are tiny
        logits[half][m] = ev;                       // unnormalized
        float sm = ev;
        #pragma unroll
        for (int o = 16; o; o >>= 1) sm += __shfl_xor_sync(0xFFFFFFFFu, sm, o);
        if ((tid & 31) == 0) wred[half][w4] = sm;
    }
    __syncthreads();

    // ---------------- F: pass-2 gathers, e-quad fp16, inv folded in ----------------
    // lane = 4*p + eq : p in 0..7 handles s = it*8+p, eq picks 4 e's (8B of halves).
    {
        int w = tid >> 5;
        int fh = w >> 2, wl = w & 3;
        int lane = tid & 31, p = lane >> 2, eq = lane & 3;
        int Kf = fh ? K1 : K0;
        float inv = 1.f / (wred[fh][0] + wred[fh][1] + wred[fh][2] + wred[fh][3]);
        float4 a0 = make_float4(0.f, 0.f, 0.f, 0.f);
        float4 a1 = make_float4(0.f, 0.f, 0.f, 0.f);
        float accp = 0.f;
        for (int r = wl; r < Kf; r += 4) {
            int m = nzlist[fh][r];
            float pm = logits[fh][m] * inv;
            accp += pm;                   // lane 0's copy used
            #pragma unroll
            for (int it = 0; it < 4; it++) {
                int s = it * 8 + p;
                unsigned int wd = sidxw[fh][m * 8 + (s >> 2)];
                int idx = (wd >> (8 * (s & 3))) & 255;
                uint2 uv = *(const uint2*)&obtH[idx * 20 + eq * 4];
                float2 f0 = __half22float2(*(__half2*)&uv.x);
                float2 f1 = __half22float2(*(__half2*)&uv.y);
                float c1 = pm * (float)(s - 15);
                a0.x = fmaf(f0.x, pm, a0.x);
                a0.y = fmaf(f0.y, pm, a0.y);
                a0.z = fmaf(f1.x, pm, a0.z);
                a0.w = fmaf(f1.y, pm, a0.w);
                a1.x = fmaf(f0.x, c1, a1.x);
                a1.y = fmaf(f0.y, c1, a1.y);
                a1.z = fmaf(f1.x, c1, a1.z);
                a1.w = fmaf(f1.y, c1, a1.w);
            }
        }
        #pragma unroll
        for (int o = 16; o >= 4; o >>= 1) {
            a0.x += __shfl_xor_sync(0xFFFFFFFFu, a0.x, o);
            a0.y += __shfl_xor_sync(0xFFFFFFFFu, a0.y, o);
            a0.z += __shfl_xor_sync(0xFFFFFFFFu, a0.z, o);
            a0.w += __shfl_xor_sync(0xFFFFFFFFu, a0.w, o);
            a1.x += __shfl_xor_sync(0xFFFFFFFFu, a1.x, o);
            a1.y += __shfl_xor_sync(0xFFFFFFFFu, a1.y, o);
            a1.z += __shfl_xor_sync(0xFFFFFFFFu, a1.z, o);
            a1.w += __shfl_xor_sync(0xFFFFFFFFu, a1.w, o);
        }
        if (lane < 4) {
            *(float4*)&red0[w * 16 + eq * 4] = a0;
            *(float4*)&red1[w * 16 + eq * 4] = a1;
        }
        if (lane == 0) redp[w] = accp;
    }
    __syncthreads();

    // ---------------- G: combine -> hvec per half + closed-form graph hvec ----------------
    if (tid < 32) {
        int gh = tid >> 4, e = tid & 15;
        float O0 = 0.f, O1 = 0.f, sp = 0.f;
        #pragma unroll
        for (int wl = 0; wl < 4; wl++) {
            O0 += red0[(gh * 4 + wl) * 16 + e];
            O1 += red1[(gh * 4 + wl) * 16 + e];
            sp += redp[gh * 4 + wl];
        }
        float Z = 1.f - sp;                       // prob mass on zero rows
        float ob0 = output_biases[e];             // fp32 row v=0
        O0 += Z * 32.f * ob0;
        O1 += Z * 16.f * ob0;
        float ae = (float)(e - 7) * (1.f / 128.f);
        hs[gh][e] = uvec[gh][e] + O0 + ae * O1;
    } else if (tid < 48) {
        // graph row: stories all-zero -> o independent of probs (closed form)
        int e = tid - 32;
        float ae = (float)(e - 7) * (1.f / 128.f);
        hsg[e] = uvec[2][e] + (32.f + 16.f * ae) * output_biases[e];
    }
    __syncthreads();

    // ---------------- H: xsum[half][l] = relu(h_half@W_out) + relu(h_g@W_out) ----------------
    {
        int l = ht;
        float accO = 0.f, accG = 0.f;
        #pragma unroll
        for (int e = 0; e < EE; e++) {
            float w = W_out[e * LL + l];
            accO = fmaf(hs[half][e], w, accO);
            accG = fmaf(hsg[e], w, accG);
        }
        xsum[half][l] = fmaxf(accO, 0.f) + fmaxf(accG, 0.f);
    }
    __syncthreads();

    // ---------------- I: both rows @ W_fin, wv loads shared; partials in dead sidxw ----------------
    {
        int vq = tid & 31, lh = tid >> 5;          // 8 lh groups x 16 l
        const float4* wp = (const float4*)W_fin + (lh * 16) * 32 + vq;
        float4 aA = make_float4(0.f, 0.f, 0.f, 0.f);
        float4 aB = make_float4(0.f, 0.f, 0.f, 0.f);
        int l = lh * 16;
        #pragma unroll 1
        for (int ch = 0; ch < 8; ch++) {
            float4 w0 = wp[0];
            float4 w1 = wp[32];
            float xA0 = xsum[0][l], xA1 = xsum[0][l + 1];
            float xB0 = xsum[1][l], xB1 = xsum[1][l + 1];
            aA.x = fmaf(w0.x, xA0, aA.x); aA.y = fmaf(w0.y, xA0, aA.y);
            aA.z = fmaf(w0.z, xA0, aA.z); aA.w = fmaf(w0.w, xA0, aA.w);
            aB.x = fmaf(w0.x, xB0, aB.x); aB.y = fmaf(w0.y, xB0, aB.y);
            aB.z = fmaf(w0.z, xB0, aB.z); aB.w = fmaf(w0.w, xB0, aB.w);
            aA.x = fmaf(w1.x, xA1, aA.x); aA.y = fmaf(w1.y, xA1, aA.y);
            aA.z = fmaf(w1.z, xA1, aA.z); aA.w = fmaf(w1.w, xA1, aA.w);
            aB.x = fmaf(w1.x, xB1, aB.x); aB.y = fmaf(w1.y, xB1, aB.y);
            aB.z = fmaf(w1.z, xB1, aB.z); aB.w = fmaf(w1.w, xB1, aB.w);
            wp += 64;
            l += 2;
        }
        float4* part = (float4*)&sidxw[0][0];      // sidxw dead after F; 7.2KB used of 8KB
        if (lh > 0) {
            part[((lh - 1) * 2 + 0) * 32 + vq] = aA;
            part[((lh - 1) * 2 + 1) * 32 + vq] = aB;
        }
        __syncthreads();
        if (lh == 0) {
            #pragma unroll
            for (int j = 0; j < 7; j++) {
                float4 pa = part[(j * 2 + 0) * 32 + vq];
                float4 pb = part[(j * 2 + 1) * 32 + vq];
                aA.x += pa.x; aA.y += pa.y; aA.z += pa.z; aA.w += pa.w;
                aB.x += pb.x; aB.y += pb.y; aB.z += pb.z; aB.w += pb.w;
            }
            *(float4*)&out[(b * NN + tA) * VV + vq * 4] = aA;
            if (stB) *(float4*)&out[(b * NN + tBr) * VV + vq * 4] = aB;
        }
    }
}

extern "C" void kernel_launch(void* const* d_in, const int* in_sizes, int n_in,
                              void* d_out, int out_size)
{
    (void)in_sizes; (void)n_in; (void)out_size;
    const float* node_fts        = (const float*)d_in[0];
    const float* edge_fts        = (const float*)d_in[1];
    const float* graph_fts       = (const float*)d_in[2];
    const float* adj_mat         = (const float*)d_in[3];
    // d_in[4] hidden (unused), d_in[5] enc (computed analytically, exact)
    const float* query_biases    = (const float*)d_in[6];
    const float* stories_biases  = (const float*)d_in[7];
    const float* output_biases   = (const float*)d_in[8];
    const float* memory_contents = (const float*)d_in[9];
    // d_in[10] W_int unused (num_hops == 1)
    const float* W_out           = (const float*)d_in[11];
    const float* W_fin           = (const float*)d_in[12];

    memnet_fused2<<<BB * 64, 256>>>(node_fts, edge_fts, graph_fts, adj_mat,
                                    query_biases, stories_biases, output_biases,
                                    memory_contents, W_out, W_fin, (float*)d_out);
}